// round 2
// baseline (speedup 1.0000x reference)
#include <cuda_runtime.h>
#include <cstdint>

#define NN 512
#define LUT_N 83521            // 17^4
#define NPIX (4 * NN * NN)

// ---------------- device scratch (no dynamic allocation allowed) ----------------
__device__ int8_t g_q0[3 * LUT_N];        // stage-0 quantized LUT (1 channel, int8)
__device__ uint4  g_q1[3 * LUT_N];        // stage-1 quantized LUT (16 ch, biased u8, 16B/row)
__device__ float  g_x1[NPIX];             // stage-0 output image (integers 0..255)

__constant__ float c_samp0[108];          // (3,4,3,3)
__constant__ float c_samp1[108];
__constant__ float c_sb0[12];
__constant__ float c_sb1[12];
__constant__ float c_resw[12];

// ---------------- LUT quantization ----------------
__global__ void quant_lut0(const float* __restrict__ src) {
    int i = blockIdx.x * blockDim.x + threadIdx.x;
    if (i < 3 * LUT_N) {
        float q = rintf(src[i] * 127.0f);
        q = fminf(fmaxf(q, -127.0f), 127.0f);
        g_q0[i] = (int8_t)(int)q;
    }
}

__global__ void quant_lut1(const float* __restrict__ src) {
    int i = blockIdx.x * blockDim.x + threadIdx.x;
    if (i < 3 * LUT_N) {
        const float* s = src + (size_t)i * 16;
        unsigned w[4];
#pragma unroll
        for (int wi = 0; wi < 4; wi++) {
            unsigned acc = 0;
#pragma unroll
            for (int b = 0; b < 4; b++) {
                float q = rintf(s[wi * 4 + b] * 127.0f);
                q = fminf(fmaxf(q, -127.0f), 127.0f);
                unsigned v = (unsigned)((int)q + 128);   // biased u8 in [1,255]
                acc |= v << (b * 8);
            }
            w[wi] = acc;
        }
        g_q1[i] = make_uint4(w[0], w[1], w[2], w[3]);
    }
}

// ---------------- helpers ----------------
__device__ __forceinline__ void load_nbr(const float* __restrict__ img, int p, int q,
                                         float scale, float nb[25]) {
    int rr[5], cc[5];
#pragma unroll
    for (int i = 0; i < 5; i++) {
        rr[i] = min(max(p - 2 + i, 0), NN - 1);
        cc[i] = min(max(q - 2 + i, 0), NN - 1);
    }
#pragma unroll
    for (int i = 0; i < 5; i++)
#pragma unroll
        for (int j = 0; j < 5; j++)
            nb[i * 5 + j] = scale * __ldg(img + rr[i] * NN + cc[j]);
}

// Rotation-r sample of 4 conv channels from a 5x5 neighborhood.
// r=0: X[p+u,q+v]; r=1: X[p+v,q-u]; r=2: X[p-u,q-v]; r=3: X[p-v,q+u]
template <int R>
__device__ __forceinline__ void sample4(const float nb[25], const float* wg,
                                        const float* bias, float v[4]) {
#pragma unroll
    for (int ch = 0; ch < 4; ch++) {
        float a = bias[ch];
#pragma unroll
        for (int u = 0; u < 3; u++)
#pragma unroll
            for (int w = 0; w < 3; w++) {
                int dy = (R == 0) ? u : (R == 1) ? w : (R == 2) ? -u : -w;
                int dx = (R == 0) ? w : (R == 1) ? -u : (R == 2) ? -w : u;
                a += wg[ch * 9 + u * 3 + w] * nb[(2 + dy) * 5 + (2 + dx)];
            }
        v[ch] = a;
    }
}

// 4D simplex: quantize, sort fractional parts (desc), build 5 vertex indices + weights.
__device__ __forceinline__ void simplex(const float v[4], int verts[5], float ws[5]) {
    int la = (int)(v[0] * 0.0625f), lb = (int)(v[1] * 0.0625f);
    int lc = (int)(v[2] * 0.0625f), ld = (int)(v[3] * 0.0625f);
    float f0 = v[0] - 16.0f * la, f1 = v[1] - 16.0f * lb;
    float f2 = v[2] - 16.0f * lc, f3 = v[3] - 16.0f * ld;
    int base = la * 4913 + lb * 289 + lc * 17 + ld;
    int t0 = 4913, t1 = 289, t2 = 17, t3 = 1;
#define CSW(fa_, fb_, ta_, tb_)                         \
    { if (fa_ < fb_) { float tf = fa_; fa_ = fb_; fb_ = tf; \
                       int ti = ta_; ta_ = tb_; tb_ = ti; } }
    CSW(f0, f1, t0, t1); CSW(f2, f3, t2, t3);
    CSW(f0, f2, t0, t2); CSW(f1, f3, t1, t3);
    CSW(f1, f2, t1, t2);
#undef CSW
    ws[0] = 16.0f - f0; ws[1] = f0 - f1; ws[2] = f1 - f2; ws[3] = f2 - f3; ws[4] = f3;
    verts[0] = base;
    verts[1] = verts[0] + t0;
    verts[2] = verts[1] + t1;
    verts[3] = verts[2] + t2;
    verts[4] = verts[3] + t3;
}

// ---------------- stage 0 ----------------
template <int R>
__device__ __forceinline__ float rot_contrib0(const float nb[25], const float* wg,
                                              const float* bi, const int8_t* __restrict__ lt) {
    float v[4];
    sample4<R>(nb, wg, bi, v);
    int verts[5]; float ws[5];
    simplex(v, verts, ws);
    float dot = 0.0f;
#pragma unroll
    for (int t = 0; t < 5; t++) dot += ws[t] * (float)__ldg(lt + verts[t]);
    return dot * 0.0625f;
}

__global__ void __launch_bounds__(256) stage0_kernel(const float* __restrict__ x) {
    int q = blockIdx.x * 32 + threadIdx.x;
    int p = blockIdx.y * 8 + threadIdx.y;
    int b = blockIdx.z;
    float nb[25];
    load_nbr(x + (size_t)b * NN * NN, p, q, 255.0f, nb);

    float total = 0.0f;
    for (int s = 0; s < 3; s++) {
        const float* wg = c_samp0 + s * 36;
        const float* bi = c_sb0 + s * 4;
        const int8_t* lt = g_q0 + s * LUT_N;
        float acc = 0.0f;
        acc = rintf(acc + rot_contrib0<0>(nb, wg, bi, lt));
        acc = rintf(acc + rot_contrib0<1>(nb, wg, bi, lt));
        acc = rintf(acc + rot_contrib0<2>(nb, wg, bi, lt));
        acc = rintf(acc + rot_contrib0<3>(nb, wg, bi, lt));
        total += acc;
    }
    float o = rintf(fminf(fmaxf(total * (1.0f / 12.0f) + 127.0f, 0.0f), 255.0f));
    g_x1[(size_t)b * NN * NN + p * NN + q] = o;
}

// ---------------- stage 1 ----------------
template <int R>
__device__ __forceinline__ void rot_contrib1(const float nb1[25], const float nb0[25],
                                             const float* wg, const float* bi,
                                             const float rw[4],
                                             const uint4* __restrict__ lt, float blk[16]) {
    float vc[4], vp[4], v[4];
    sample4<R>(nb1, wg, bi, vc);
    sample4<R>(nb0, wg, bi, vp);
#pragma unroll
    for (int ch = 0; ch < 4; ch++)
        v[ch] = rw[ch] * vp[ch] + (1.0f - rw[ch]) * vc[ch];

    int verts[5]; float ws[5];
    simplex(v, verts, ws);

    float c[16];
#pragma unroll
    for (int k = 0; k < 16; k++) c[k] = 0.0f;
#pragma unroll
    for (int t = 0; t < 5; t++) {
        uint4 wv = __ldg(lt + verts[t]);
        float wt = ws[t];
        unsigned wd0 = wv.x, wd1 = wv.y, wd2 = wv.z, wd3 = wv.w;
#pragma unroll
        for (int k = 0; k < 16; k++) {
            unsigned word = (k < 4) ? wd0 : (k < 8) ? wd1 : (k < 12) ? wd2 : wd3;
            // biased u8 -> float via magic number: exact
            float m = __uint_as_float(__byte_perm(word, 0x4B000000u, 0x7540u + (k & 3)));
            c[k] += wt * (m - 8388736.0f);
        }
    }
#pragma unroll
    for (int i = 0; i < 4; i++)
#pragma unroll
        for (int j = 0; j < 4; j++) {
            int k = (R == 0) ? (i * 4 + j)
                  : (R == 1) ? ((3 - j) * 4 + i)
                  : (R == 2) ? ((3 - i) * 4 + (3 - j))
                             : (j * 4 + (3 - i));
            blk[i * 4 + j] = rintf(blk[i * 4 + j] + c[k] * 0.0625f);
        }
}

__global__ void __launch_bounds__(256) stage1_kernel(const float* __restrict__ x,
                                                     float* __restrict__ out) {
    int q = blockIdx.x * 32 + threadIdx.x;
    int p = blockIdx.y * 8 + threadIdx.y;
    int b = blockIdx.z;

    float nb1[25], nb0[25];
    load_nbr(g_x1 + (size_t)b * NN * NN, p, q, 1.0f, nb1);
    load_nbr(x + (size_t)b * NN * NN, p, q, 255.0f, nb0);

    float fin[16];
#pragma unroll
    for (int k = 0; k < 16; k++) fin[k] = 0.0f;

    for (int s = 0; s < 3; s++) {
        const float* wg = c_samp1 + s * 36;
        const float* bi = c_sb1 + s * 4;
        float rw[4];
#pragma unroll
        for (int ch = 0; ch < 4; ch++)
            rw[ch] = fminf(fmaxf(c_resw[s * 4 + ch], 0.0f), 1.0f);
        const uint4* lt = g_q1 + s * LUT_N;

        float blk[16];
#pragma unroll
        for (int k = 0; k < 16; k++) blk[k] = 0.0f;
        rot_contrib1<0>(nb1, nb0, wg, bi, rw, lt, blk);
        rot_contrib1<1>(nb1, nb0, wg, bi, rw, lt, blk);
        rot_contrib1<2>(nb1, nb0, wg, bi, rw, lt, blk);
        rot_contrib1<3>(nb1, nb0, wg, bi, rw, lt, blk);
#pragma unroll
        for (int k = 0; k < 16; k++) fin[k] += blk[k];
    }

    float* op = out + ((size_t)b << 22) + (size_t)(4 * p) * 2048 + 4 * q;
#pragma unroll
    for (int i = 0; i < 4; i++) {
        float4 o;
        o.x = rintf(fminf(fmaxf(fin[i * 4 + 0] * (1.0f / 3.0f), 0.0f), 255.0f)) * (1.0f / 255.0f);
        o.y = rintf(fminf(fmaxf(fin[i * 4 + 1] * (1.0f / 3.0f), 0.0f), 255.0f)) * (1.0f / 255.0f);
        o.z = rintf(fminf(fmaxf(fin[i * 4 + 2] * (1.0f / 3.0f), 0.0f), 255.0f)) * (1.0f / 255.0f);
        o.w = rintf(fminf(fmaxf(fin[i * 4 + 3] * (1.0f / 3.0f), 0.0f), 255.0f)) * (1.0f / 255.0f);
        *reinterpret_cast<float4*>(op + (size_t)i * 2048) = o;
    }
}

// ---------------- launch ----------------
extern "C" void kernel_launch(void* const* d_in, const int* in_sizes, int n_in,
                              void* d_out, int out_size) {
    const float* x     = (const float*)d_in[0];
    const float* lut0  = (const float*)d_in[1];
    const float* lut1  = (const float*)d_in[2];
    const float* samp0 = (const float*)d_in[3];
    const float* samp1 = (const float*)d_in[4];
    const float* sb0   = (const float*)d_in[5];
    const float* sb1   = (const float*)d_in[6];
    const float* resw  = (const float*)d_in[7];

    cudaMemcpyToSymbolAsync(c_samp0, samp0, 108 * sizeof(float), 0, cudaMemcpyDeviceToDevice);
    cudaMemcpyToSymbolAsync(c_samp1, samp1, 108 * sizeof(float), 0, cudaMemcpyDeviceToDevice);
    cudaMemcpyToSymbolAsync(c_sb0,   sb0,    12 * sizeof(float), 0, cudaMemcpyDeviceToDevice);
    cudaMemcpyToSymbolAsync(c_sb1,   sb1,    12 * sizeof(float), 0, cudaMemcpyDeviceToDevice);
    cudaMemcpyToSymbolAsync(c_resw,  resw,   12 * sizeof(float), 0, cudaMemcpyDeviceToDevice);

    int nlut = 3 * LUT_N;
    quant_lut0<<<(nlut + 255) / 256, 256>>>(lut0);
    quant_lut1<<<(nlut + 255) / 256, 256>>>(lut1);

    dim3 blk(32, 8, 1);
    dim3 grd(NN / 32, NN / 8, 4);
    stage0_kernel<<<grd, blk>>>(x);
    stage1_kernel<<<grd, blk>>>(x, (float*)d_out);
}

// round 3
// speedup vs baseline: 1.2953x; 1.2953x over previous
#include <cuda_runtime.h>
#include <cstdint>

#define NN 512
#define LUT_N 83521            // 17^4
#define NPIX (4 * NN * NN)

// ---------------- device scratch ----------------
__device__ int8_t g_q0[3 * LUT_N];        // stage-0 quantized LUT (int8)
__device__ uint4  g_q1[3 * LUT_N];        // stage-1 quantized LUT (16 ch, biased u8, 16B/row)
__device__ float  g_x1[NPIX];             // stage-0 output image (integers 0..255)

__constant__ float c_samp0[108];
__constant__ float c_samp1[108];
__constant__ float c_sb0[12];
__constant__ float c_sb1[12];
__constant__ float c_resw[12];

// ---------------- f32x2 helpers ----------------
__device__ __forceinline__ unsigned long long pack2(unsigned lo, unsigned hi) {
    unsigned long long d;
    asm("mov.b64 %0, {%1, %2};" : "=l"(d) : "r"(lo), "r"(hi));
    return d;
}
__device__ __forceinline__ void unpack2(unsigned long long v, float& lo, float& hi) {
    asm("mov.b64 {%0, %1}, %2;" : "=f"(lo), "=f"(hi) : "l"(v));
}
__device__ __forceinline__ unsigned long long fadd2(unsigned long long a, unsigned long long b) {
    unsigned long long d;
    asm("add.rn.f32x2 %0, %1, %2;" : "=l"(d) : "l"(a), "l"(b));
    return d;
}
__device__ __forceinline__ unsigned long long ffma2(unsigned long long a, unsigned long long b,
                                                    unsigned long long c) {
    unsigned long long d;
    asm("fma.rn.f32x2 %0, %1, %2, %3;" : "=l"(d) : "l"(a), "l"(b), "l"(c));
    return d;
}

// ---------------- LUT quantization ----------------
__global__ void quant_lut0(const float* __restrict__ src) {
    int i = blockIdx.x * blockDim.x + threadIdx.x;
    if (i < 3 * LUT_N) {
        float q = rintf(src[i] * 127.0f);
        q = fminf(fmaxf(q, -127.0f), 127.0f);
        g_q0[i] = (int8_t)(int)q;
    }
}

__global__ void quant_lut1(const float* __restrict__ src) {
    int i = blockIdx.x * blockDim.x + threadIdx.x;
    if (i < 3 * LUT_N) {
        const float* s = src + (size_t)i * 16;
        unsigned w[4];
#pragma unroll
        for (int wi = 0; wi < 4; wi++) {
            unsigned acc = 0;
#pragma unroll
            for (int b = 0; b < 4; b++) {
                float q = rintf(s[wi * 4 + b] * 127.0f);
                q = fminf(fmaxf(q, -127.0f), 127.0f);
                unsigned v = (unsigned)((int)q + 128);   // biased u8
                acc |= v << (b * 8);
            }
            w[wi] = acc;
        }
        g_q1[i] = make_uint4(w[0], w[1], w[2], w[3]);
    }
}

// ---------------- helpers ----------------
__device__ __forceinline__ void load_nbr(const float* __restrict__ img, int p, int q,
                                         float scale, float nb[25]) {
    int rr[5], cc[5];
#pragma unroll
    for (int i = 0; i < 5; i++) {
        rr[i] = min(max(p - 2 + i, 0), NN - 1);
        cc[i] = min(max(q - 2 + i, 0), NN - 1);
    }
#pragma unroll
    for (int i = 0; i < 5; i++)
#pragma unroll
        for (int j = 0; j < 5; j++)
            nb[i * 5 + j] = scale * __ldg(img + rr[i] * NN + cc[j]);
}

// Rotation-r sample: r=0: X[p+u,q+v]; r=1: X[p+v,q-u]; r=2: X[p-u,q-v]; r=3: X[p-v,q+u]
template <int R>
__device__ __forceinline__ void sample4(const float nb[25], const float* wg,
                                        const float* bias, float v[4]) {
#pragma unroll
    for (int ch = 0; ch < 4; ch++) {
        float a = bias[ch];
#pragma unroll
        for (int u = 0; u < 3; u++)
#pragma unroll
            for (int w = 0; w < 3; w++) {
                int dy = (R == 0) ? u : (R == 1) ? w : (R == 2) ? -u : -w;
                int dx = (R == 0) ? w : (R == 1) ? -u : (R == 2) ? -w : u;
                a += wg[ch * 9 + u * 3 + w] * nb[(2 + dy) * 5 + (2 + dx)];
            }
        v[ch] = a;
    }
}

// 4D simplex; ws pre-scaled by 1/16 (exact)
__device__ __forceinline__ void simplex(const float v[4], int verts[5], float ws[5]) {
    int la = (int)(v[0] * 0.0625f), lb = (int)(v[1] * 0.0625f);
    int lc = (int)(v[2] * 0.0625f), ld = (int)(v[3] * 0.0625f);
    float f0 = v[0] - 16.0f * la, f1 = v[1] - 16.0f * lb;
    float f2 = v[2] - 16.0f * lc, f3 = v[3] - 16.0f * ld;
    int base = la * 4913 + lb * 289 + lc * 17 + ld;
    int t0 = 4913, t1 = 289, t2 = 17, t3 = 1;
#define CSW(fa_, fb_, ta_, tb_)                         \
    { if (fa_ < fb_) { float tf = fa_; fa_ = fb_; fb_ = tf; \
                       int ti = ta_; ta_ = tb_; tb_ = ti; } }
    CSW(f0, f1, t0, t1); CSW(f2, f3, t2, t3);
    CSW(f0, f2, t0, t2); CSW(f1, f3, t1, t3);
    CSW(f1, f2, t1, t2);
#undef CSW
    ws[0] = (16.0f - f0) * 0.0625f;
    ws[1] = (f0 - f1) * 0.0625f;
    ws[2] = (f1 - f2) * 0.0625f;
    ws[3] = (f2 - f3) * 0.0625f;
    ws[4] = f3 * 0.0625f;
    verts[0] = base;
    verts[1] = verts[0] + t0;
    verts[2] = verts[1] + t1;
    verts[3] = verts[2] + t2;
    verts[4] = verts[3] + t3;
}

// ---------------- stage 0 ----------------
template <int R>
__device__ __forceinline__ float rot_contrib0(const float nb[25], const float* wg,
                                              const float* bi, const int8_t* __restrict__ lt) {
    float v[4];
    sample4<R>(nb, wg, bi, v);
    int verts[5]; float ws[5];
    simplex(v, verts, ws);
    float dot = 0.0f;
#pragma unroll
    for (int t = 0; t < 5; t++) dot += ws[t] * (float)__ldg(lt + verts[t]);
    return dot;
}

__global__ void __launch_bounds__(256, 3) stage0_kernel(const float* __restrict__ x) {
    int q = blockIdx.x * 32 + threadIdx.x;
    int p = blockIdx.y * 8 + threadIdx.y;
    int b = blockIdx.z;
    float nb[25];
    load_nbr(x + (size_t)b * NN * NN, p, q, 255.0f, nb);

    float total = 0.0f;
    for (int s = 0; s < 3; s++) {
        const float* wg = c_samp0 + s * 36;
        const float* bi = c_sb0 + s * 4;
        const int8_t* lt = g_q0 + s * LUT_N;
        float acc = 0.0f;
        acc = rintf(acc + rot_contrib0<0>(nb, wg, bi, lt));
        acc = rintf(acc + rot_contrib0<1>(nb, wg, bi, lt));
        acc = rintf(acc + rot_contrib0<2>(nb, wg, bi, lt));
        acc = rintf(acc + rot_contrib0<3>(nb, wg, bi, lt));
        total += acc;
    }
    float o = rintf(fminf(fmaxf(total * (1.0f / 12.0f) + 127.0f, 0.0f), 255.0f));
    g_x1[(size_t)b * NN * NN + p * NN + q] = o;
}

// ---------------- stage 1 ----------------
template <int R>
__device__ __forceinline__ void rot_contrib1(const float nb1[25], const float nb0[25],
                                             const float* wg, const float* bi,
                                             const float rw[4],
                                             const uint4* __restrict__ lt, float blk[16]) {
    float vc[4], vp[4], v[4];
    sample4<R>(nb1, wg, bi, vc);
    sample4<R>(nb0, wg, bi, vp);
#pragma unroll
    for (int ch = 0; ch < 4; ch++)
        v[ch] = vc[ch] + rw[ch] * (vp[ch] - vc[ch]);

    int verts[5]; float ws[5];
    simplex(v, verts, ws);

    // packed f32x2 accumulators: 8 pairs = 16 channels
    unsigned long long c2[8];
#pragma unroll
    for (int pidx = 0; pidx < 8; pidx++) c2[pidx] = 0ull;
    const unsigned long long B2 = pack2(0xCB000080u, 0xCB000080u);  // (-8388736, -8388736)

#pragma unroll
    for (int t = 0; t < 5; t++) {
        uint4 wv = __ldg(lt + verts[t]);
        unsigned wtb = __float_as_uint(ws[t]);
        unsigned long long wt2 = pack2(wtb, wtb);
#pragma unroll
        for (int pidx = 0; pidx < 8; pidx++) {
            unsigned word = (pidx < 2) ? wv.x : (pidx < 4) ? wv.y : (pidx < 6) ? wv.z : wv.w;
            int kk = (pidx & 1) * 2;
            unsigned lo = __byte_perm(word, 0x4B000000u, 0x7540u + kk);
            unsigned hi = __byte_perm(word, 0x4B000000u, 0x7541u + kk);
            unsigned long long m2 = fadd2(pack2(lo, hi), B2);  // exact (byte-128) per lane
            c2[pidx] = ffma2(m2, wt2, c2[pidx]);
        }
    }

    float c[16];
#pragma unroll
    for (int pidx = 0; pidx < 8; pidx++) unpack2(c2[pidx], c[2 * pidx], c[2 * pidx + 1]);

#pragma unroll
    for (int i = 0; i < 4; i++)
#pragma unroll
        for (int j = 0; j < 4; j++) {
            int k = (R == 0) ? (i * 4 + j)
                  : (R == 1) ? ((3 - j) * 4 + i)
                  : (R == 2) ? ((3 - i) * 4 + (3 - j))
                             : (j * 4 + (3 - i));
            blk[i * 4 + j] = rintf(blk[i * 4 + j] + c[k]);
        }
}

__global__ void __launch_bounds__(256, 2) stage1_kernel(const float* __restrict__ x,
                                                        float* __restrict__ out) {
    int q = blockIdx.x * 32 + threadIdx.x;
    int p = blockIdx.y * 8 + threadIdx.y;
    int b = blockIdx.z;

    float nb1[25], nb0[25];
    load_nbr(g_x1 + (size_t)b * NN * NN, p, q, 1.0f, nb1);
    load_nbr(x + (size_t)b * NN * NN, p, q, 255.0f, nb0);

    float fin[16];
#pragma unroll
    for (int k = 0; k < 16; k++) fin[k] = 0.0f;

    for (int s = 0; s < 3; s++) {
        const float* wg = c_samp1 + s * 36;
        const float* bi = c_sb1 + s * 4;
        float rw[4];
#pragma unroll
        for (int ch = 0; ch < 4; ch++)
            rw[ch] = fminf(fmaxf(c_resw[s * 4 + ch], 0.0f), 1.0f);
        const uint4* lt = g_q1 + s * LUT_N;

        float blk[16];
#pragma unroll
        for (int k = 0; k < 16; k++) blk[k] = 0.0f;
        rot_contrib1<0>(nb1, nb0, wg, bi, rw, lt, blk);
        rot_contrib1<1>(nb1, nb0, wg, bi, rw, lt, blk);
        rot_contrib1<2>(nb1, nb0, wg, bi, rw, lt, blk);
        rot_contrib1<3>(nb1, nb0, wg, bi, rw, lt, blk);
#pragma unroll
        for (int k = 0; k < 16; k++) fin[k] += blk[k];
    }

    float* op = out + ((size_t)b << 22) + (size_t)(4 * p) * 2048 + 4 * q;
#pragma unroll
    for (int i = 0; i < 4; i++) {
        float4 o;
        o.x = rintf(fminf(fmaxf(fin[i * 4 + 0] * (1.0f / 3.0f), 0.0f), 255.0f)) * (1.0f / 255.0f);
        o.y = rintf(fminf(fmaxf(fin[i * 4 + 1] * (1.0f / 3.0f), 0.0f), 255.0f)) * (1.0f / 255.0f);
        o.z = rintf(fminf(fmaxf(fin[i * 4 + 2] * (1.0f / 3.0f), 0.0f), 255.0f)) * (1.0f / 255.0f);
        o.w = rintf(fminf(fmaxf(fin[i * 4 + 3] * (1.0f / 3.0f), 0.0f), 255.0f)) * (1.0f / 255.0f);
        *reinterpret_cast<float4*>(op + (size_t)i * 2048) = o;
    }
}

// ---------------- launch ----------------
extern "C" void kernel_launch(void* const* d_in, const int* in_sizes, int n_in,
                              void* d_out, int out_size) {
    const float* x     = (const float*)d_in[0];
    const float* lut0  = (const float*)d_in[1];
    const float* lut1  = (const float*)d_in[2];
    const float* samp0 = (const float*)d_in[3];
    const float* samp1 = (const float*)d_in[4];
    const float* sb0   = (const float*)d_in[5];
    const float* sb1   = (const float*)d_in[6];
    const float* resw  = (const float*)d_in[7];

    cudaMemcpyToSymbolAsync(c_samp0, samp0, 108 * sizeof(float), 0, cudaMemcpyDeviceToDevice);
    cudaMemcpyToSymbolAsync(c_samp1, samp1, 108 * sizeof(float), 0, cudaMemcpyDeviceToDevice);
    cudaMemcpyToSymbolAsync(c_sb0,   sb0,    12 * sizeof(float), 0, cudaMemcpyDeviceToDevice);
    cudaMemcpyToSymbolAsync(c_sb1,   sb1,    12 * sizeof(float), 0, cudaMemcpyDeviceToDevice);
    cudaMemcpyToSymbolAsync(c_resw,  resw,   12 * sizeof(float), 0, cudaMemcpyDeviceToDevice);

    int nlut = 3 * LUT_N;
    quant_lut0<<<(nlut + 255) / 256, 256>>>(lut0);
    quant_lut1<<<(nlut + 255) / 256, 256>>>(lut1);

    dim3 blk(32, 8, 1);
    dim3 grd(NN / 32, NN / 8, 4);
    stage0_kernel<<<grd, blk>>>(x);
    stage1_kernel<<<grd, blk>>>(x, (float*)d_out);
}

// round 4
// speedup vs baseline: 1.3254x; 1.0233x over previous
#include <cuda_runtime.h>
#include <cstdint>

#define NN 512
#define LUT_N 83521            // 17^4
#define NPIX (4 * NN * NN)

// ---------------- device scratch ----------------
__device__ int8_t g_q0[3 * LUT_N];        // stage-0 quantized LUT (int8)
__device__ uint4  g_q1[3 * LUT_N];        // stage-1 quantized LUT (16 ch, biased u8, 16B/row)
__device__ float  g_x1[NPIX];             // stage-0 output image (integers 0..255)

__constant__ float c_samp0[108];
__constant__ float c_samp1[108];
__constant__ float c_sb0[12];
__constant__ float c_sb1[12];
__constant__ float c_resw[12];

// ---------------- f32x2 helpers ----------------
__device__ __forceinline__ unsigned long long pack2(unsigned lo, unsigned hi) {
    unsigned long long d;
    asm("mov.b64 %0, {%1, %2};" : "=l"(d) : "r"(lo), "r"(hi));
    return d;
}
__device__ __forceinline__ unsigned long long pack2f(float lo, float hi) {
    return pack2(__float_as_uint(lo), __float_as_uint(hi));
}
__device__ __forceinline__ void unpack2(unsigned long long v, float& lo, float& hi) {
    asm("mov.b64 {%0, %1}, %2;" : "=f"(lo), "=f"(hi) : "l"(v));
}
__device__ __forceinline__ unsigned long long fadd2(unsigned long long a, unsigned long long b) {
    unsigned long long d;
    asm("add.rn.f32x2 %0, %1, %2;" : "=l"(d) : "l"(a), "l"(b));
    return d;
}
__device__ __forceinline__ unsigned long long ffma2(unsigned long long a, unsigned long long b,
                                                    unsigned long long c) {
    unsigned long long d;
    asm("fma.rn.f32x2 %0, %1, %2, %3;" : "=l"(d) : "l"(a), "l"(b), "l"(c));
    return d;
}

// ---------------- LUT quantization ----------------
__global__ void quant_lut0(const float* __restrict__ src) {
    int i = blockIdx.x * blockDim.x + threadIdx.x;
    if (i < 3 * LUT_N) {
        float q = rintf(src[i] * 127.0f);
        q = fminf(fmaxf(q, -127.0f), 127.0f);
        g_q0[i] = (int8_t)(int)q;
    }
}

__global__ void quant_lut1(const float* __restrict__ src) {
    int i = blockIdx.x * blockDim.x + threadIdx.x;
    if (i < 3 * LUT_N) {
        const float* s = src + (size_t)i * 16;
        unsigned w[4];
#pragma unroll
        for (int wi = 0; wi < 4; wi++) {
            unsigned acc = 0;
#pragma unroll
            for (int b = 0; b < 4; b++) {
                float q = rintf(s[wi * 4 + b] * 127.0f);
                q = fminf(fmaxf(q, -127.0f), 127.0f);
                unsigned v = (unsigned)((int)q + 128);   // biased u8
                acc |= v << (b * 8);
            }
            w[wi] = acc;
        }
        g_q1[i] = make_uint4(w[0], w[1], w[2], w[3]);
    }
}

// ---------------- helpers ----------------
__device__ __forceinline__ void load_nbr(const float* __restrict__ img, int p, int q,
                                         float scale, float nb[25]) {
    int rr[5], cc[5];
#pragma unroll
    for (int i = 0; i < 5; i++) {
        rr[i] = min(max(p - 2 + i, 0), NN - 1);
        cc[i] = min(max(q - 2 + i, 0), NN - 1);
    }
#pragma unroll
    for (int i = 0; i < 5; i++)
#pragma unroll
        for (int j = 0; j < 5; j++)
            nb[i * 5 + j] = scale * __ldg(img + rr[i] * NN + cc[j]);
}

// Rotation-r tap position in the 5x5 neighborhood.
// r=0: X[p+u,q+v]; r=1: X[p+v,q-u]; r=2: X[p-u,q-v]; r=3: X[p-v,q+u]
__device__ __forceinline__ constexpr int nb_idx(int R, int u, int w) {
    int dy = (R == 0) ? u : (R == 1) ? w : (R == 2) ? -u : -w;
    int dx = (R == 0) ? w : (R == 1) ? -u : (R == 2) ? -w : u;
    return (2 + dy) * 5 + (2 + dx);
}

template <int R>
__device__ __forceinline__ void sample4(const float nb[25], const float* wg,
                                        const float* bias, float v[4]) {
#pragma unroll
    for (int ch = 0; ch < 4; ch++) {
        float a = bias[ch];
#pragma unroll
        for (int u = 0; u < 3; u++)
#pragma unroll
            for (int w = 0; w < 3; w++)
                a += wg[ch * 9 + u * 3 + w] * nb[nb_idx(R, u, w)];
        v[ch] = a;
    }
}

// 4D simplex; ws pre-scaled by 1/16 (exact)
__device__ __forceinline__ void simplex(const float v[4], int verts[5], float ws[5]) {
    int la = (int)(v[0] * 0.0625f), lb = (int)(v[1] * 0.0625f);
    int lc = (int)(v[2] * 0.0625f), ld = (int)(v[3] * 0.0625f);
    float f0 = v[0] - 16.0f * la, f1 = v[1] - 16.0f * lb;
    float f2 = v[2] - 16.0f * lc, f3 = v[3] - 16.0f * ld;
    int base = la * 4913 + lb * 289 + lc * 17 + ld;
    int t0 = 4913, t1 = 289, t2 = 17, t3 = 1;
#define CSW(fa_, fb_, ta_, tb_)                         \
    { if (fa_ < fb_) { float tf = fa_; fa_ = fb_; fb_ = tf; \
                       int ti = ta_; ta_ = tb_; tb_ = ti; } }
    CSW(f0, f1, t0, t1); CSW(f2, f3, t2, t3);
    CSW(f0, f2, t0, t2); CSW(f1, f3, t1, t3);
    CSW(f1, f2, t1, t2);
#undef CSW
    ws[0] = (16.0f - f0) * 0.0625f;
    ws[1] = (f0 - f1) * 0.0625f;
    ws[2] = (f1 - f2) * 0.0625f;
    ws[3] = (f2 - f3) * 0.0625f;
    ws[4] = f3 * 0.0625f;
    verts[0] = base;
    verts[1] = verts[0] + t0;
    verts[2] = verts[1] + t1;
    verts[3] = verts[2] + t2;
    verts[4] = verts[3] + t3;
}

// ---------------- stage 0 (unchanged from R3) ----------------
template <int R>
__device__ __forceinline__ float rot_contrib0(const float nb[25], const float* wg,
                                              const float* bi, const int8_t* __restrict__ lt) {
    float v[4];
    sample4<R>(nb, wg, bi, v);
    int verts[5]; float ws[5];
    simplex(v, verts, ws);
    float dot = 0.0f;
#pragma unroll
    for (int t = 0; t < 5; t++) dot += ws[t] * (float)__ldg(lt + verts[t]);
    return dot;
}

__global__ void __launch_bounds__(256, 3) stage0_kernel(const float* __restrict__ x) {
    int q = blockIdx.x * 32 + threadIdx.x;
    int p = blockIdx.y * 8 + threadIdx.y;
    int b = blockIdx.z;
    float nb[25];
    load_nbr(x + (size_t)b * NN * NN, p, q, 255.0f, nb);

    float total = 0.0f;
    for (int s = 0; s < 3; s++) {
        const float* wg = c_samp0 + s * 36;
        const float* bi = c_sb0 + s * 4;
        const int8_t* lt = g_q0 + s * LUT_N;
        float acc = 0.0f;
        acc = rintf(acc + rot_contrib0<0>(nb, wg, bi, lt));
        acc = rintf(acc + rot_contrib0<1>(nb, wg, bi, lt));
        acc = rintf(acc + rot_contrib0<2>(nb, wg, bi, lt));
        acc = rintf(acc + rot_contrib0<3>(nb, wg, bi, lt));
        total += acc;
    }
    float o = rintf(fminf(fmaxf(total * (1.0f / 12.0f) + 127.0f, 0.0f), 255.0f));
    g_x1[(size_t)b * NN * NN + p * NN + q] = o;
}

// ---------------- stage 1 ----------------
// accumulate one rotation's 5 gathered vertices into blk (with rotation perm + ste_round)
template <int R>
__device__ __forceinline__ void acc_rot1(const uint4 d[5], const float ws[5], float blk[16]) {
    unsigned long long c2[8];
#pragma unroll
    for (int pidx = 0; pidx < 8; pidx++) c2[pidx] = 0ull;
    const unsigned long long B2 = pack2(0xCB000080u, 0xCB000080u);  // (-8388736, -8388736)

#pragma unroll
    for (int t = 0; t < 5; t++) {
        unsigned wtb = __float_as_uint(ws[t]);
        unsigned long long wt2 = pack2(wtb, wtb);
#pragma unroll
        for (int pidx = 0; pidx < 8; pidx++) {
            unsigned word = (pidx < 2) ? d[t].x : (pidx < 4) ? d[t].y
                          : (pidx < 6) ? d[t].z : d[t].w;
            int kk = (pidx & 1) * 2;
            unsigned lo = __byte_perm(word, 0x4B000000u, 0x7540u + kk);
            unsigned hi = __byte_perm(word, 0x4B000000u, 0x7541u + kk);
            unsigned long long m2 = fadd2(pack2(lo, hi), B2);  // exact (byte-128)
            c2[pidx] = ffma2(m2, wt2, c2[pidx]);
        }
    }

    float c[16];
#pragma unroll
    for (int pidx = 0; pidx < 8; pidx++) unpack2(c2[pidx], c[2 * pidx], c[2 * pidx + 1]);

#pragma unroll
    for (int i = 0; i < 4; i++)
#pragma unroll
        for (int j = 0; j < 4; j++) {
            int k = (R == 0) ? (i * 4 + j)
                  : (R == 1) ? ((3 - j) * 4 + i)
                  : (R == 2) ? ((3 - i) * 4 + (3 - j))
                             : (j * 4 + (3 - i));
            blk[i * 4 + j] = rintf(blk[i * 4 + j] + c[k]);
        }
}

__global__ void __launch_bounds__(256, 2) stage1_kernel(const float* __restrict__ x,
                                                        float* __restrict__ out) {
    int q = blockIdx.x * 32 + threadIdx.x;
    int p = blockIdx.y * 8 + threadIdx.y;
    int b = blockIdx.z;

    // packed neighborhood: lane0 = current image (g_x1), lane1 = prev image (255*x)
    unsigned long long pnb[25];
    {
        const float* img1 = g_x1 + (size_t)b * NN * NN;
        const float* img0 = x + (size_t)b * NN * NN;
        int rr[5], cc[5];
#pragma unroll
        for (int i = 0; i < 5; i++) {
            rr[i] = min(max(p - 2 + i, 0), NN - 1);
            cc[i] = min(max(q - 2 + i, 0), NN - 1);
        }
#pragma unroll
        for (int i = 0; i < 5; i++)
#pragma unroll
            for (int j = 0; j < 5; j++) {
                float v1 = __ldg(img1 + rr[i] * NN + cc[j]);
                float v0 = 255.0f * __ldg(img0 + rr[i] * NN + cc[j]);
                pnb[i * 5 + j] = pack2f(v1, v0);
            }
    }

    float fin[16];
#pragma unroll
    for (int k = 0; k < 16; k++) fin[k] = 0.0f;

#pragma unroll
    for (int s = 0; s < 3; s++) {
        const float* wg = c_samp1 + s * 36;
        const float* bi = c_sb1 + s * 4;
        const uint4* lt = g_q1 + s * LUT_N;

        // ---- paired conv (cur, prev share weights), channel-outer ----
        float v[4][4];   // [R][ch], blended
#pragma unroll
        for (int ch = 0; ch < 4; ch++) {
            unsigned long long W2[9];
#pragma unroll
            for (int t = 0; t < 9; t++) {
                float wv = wg[ch * 9 + t];
                W2[t] = pack2f(wv, wv);
            }
            float bv = bi[ch];
            unsigned long long B2b = pack2f(bv, bv);
            float rwc = fminf(fmaxf(c_resw[s * 4 + ch], 0.0f), 1.0f);
#pragma unroll
            for (int R = 0; R < 4; R++) {
                unsigned long long a2 = B2b;
#pragma unroll
                for (int u = 0; u < 3; u++)
#pragma unroll
                    for (int w = 0; w < 3; w++)
                        a2 = ffma2(W2[u * 3 + w], pnb[nb_idx(R, u, w)], a2);
                float vc, vp;
                unpack2(a2, vc, vp);
                v[R][ch] = vc + rwc * (vp - vc);
            }
        }

        // ---- simplexes for all 4 rotations ----
        int vt[4][5]; float wss[4][5];
#pragma unroll
        for (int R = 0; R < 4; R++) simplex(v[R], vt[R], wss[R]);

        // ---- pipelined gather + accumulate (one batch ahead) ----
        uint4 d0[5], d1[5];
#pragma unroll
        for (int t = 0; t < 5; t++) d0[t] = __ldg(lt + vt[0][t]);
#pragma unroll
        for (int t = 0; t < 5; t++) d1[t] = __ldg(lt + vt[1][t]);

        float blk[16];
#pragma unroll
        for (int k = 0; k < 16; k++) blk[k] = 0.0f;

        acc_rot1<0>(d0, wss[0], blk);
#pragma unroll
        for (int t = 0; t < 5; t++) d0[t] = __ldg(lt + vt[2][t]);
        acc_rot1<1>(d1, wss[1], blk);
#pragma unroll
        for (int t = 0; t < 5; t++) d1[t] = __ldg(lt + vt[3][t]);
        acc_rot1<2>(d0, wss[2], blk);
        acc_rot1<3>(d1, wss[3], blk);

#pragma unroll
        for (int k = 0; k < 16; k++) fin[k] += blk[k];
    }

    float* op = out + ((size_t)b << 22) + (size_t)(4 * p) * 2048 + 4 * q;
#pragma unroll
    for (int i = 0; i < 4; i++) {
        float4 o;
        o.x = rintf(fminf(fmaxf(fin[i * 4 + 0] * (1.0f / 3.0f), 0.0f), 255.0f)) * (1.0f / 255.0f);
        o.y = rintf(fminf(fmaxf(fin[i * 4 + 1] * (1.0f / 3.0f), 0.0f), 255.0f)) * (1.0f / 255.0f);
        o.z = rintf(fminf(fmaxf(fin[i * 4 + 2] * (1.0f / 3.0f), 0.0f), 255.0f)) * (1.0f / 255.0f);
        o.w = rintf(fminf(fmaxf(fin[i * 4 + 3] * (1.0f / 3.0f), 0.0f), 255.0f)) * (1.0f / 255.0f);
        *reinterpret_cast<float4*>(op + (size_t)i * 2048) = o;
    }
}

// ---------------- launch ----------------
extern "C" void kernel_launch(void* const* d_in, const int* in_sizes, int n_in,
                              void* d_out, int out_size) {
    const float* x     = (const float*)d_in[0];
    const float* lut0  = (const float*)d_in[1];
    const float* lut1  = (const float*)d_in[2];
    const float* samp0 = (const float*)d_in[3];
    const float* samp1 = (const float*)d_in[4];
    const float* sb0   = (const float*)d_in[5];
    const float* sb1   = (const float*)d_in[6];
    const float* resw  = (const float*)d_in[7];

    cudaMemcpyToSymbolAsync(c_samp0, samp0, 108 * sizeof(float), 0, cudaMemcpyDeviceToDevice);
    cudaMemcpyToSymbolAsync(c_samp1, samp1, 108 * sizeof(float), 0, cudaMemcpyDeviceToDevice);
    cudaMemcpyToSymbolAsync(c_sb0,   sb0,    12 * sizeof(float), 0, cudaMemcpyDeviceToDevice);
    cudaMemcpyToSymbolAsync(c_sb1,   sb1,    12 * sizeof(float), 0, cudaMemcpyDeviceToDevice);
    cudaMemcpyToSymbolAsync(c_resw,  resw,   12 * sizeof(float), 0, cudaMemcpyDeviceToDevice);

    int nlut = 3 * LUT_N;
    quant_lut0<<<(nlut + 255) / 256, 256>>>(lut0);
    quant_lut1<<<(nlut + 255) / 256, 256>>>(lut1);

    dim3 blk(32, 8, 1);
    dim3 grd(NN / 32, NN / 8, 4);
    stage0_kernel<<<grd, blk>>>(x);
    stage1_kernel<<<grd, blk>>>(x, (float*)d_out);
}